// round 1
// baseline (speedup 1.0000x reference)
#include <cuda_runtime.h>
#include <cuda_bf16.h>
#include <math.h>

// ----------------------------------------------------------------------------
// CapacityRouter: logits = x[N,1024] @ W[1024,64]; softmax; top-2; ordered
// capacity masking (capacity = N*K/E*1.25); outputs concatenated as float32:
//   [ idx (N*2) | weights (N*2) | mask (N*2) | expert_counters (64) | dropped (1) ]
// ----------------------------------------------------------------------------

#define HD 1024
#define NE 64
#define TOPK 2
#define KC 128          // k-chunk held in shared memory
#define TPB 256         // threads per block (1 token per thread)
#define NB2 256         // blocks for the capacity pipeline

__device__ int g_hist[NB2 * NE];
__device__ int g_base[NB2 * NE];

__device__ __forceinline__ unsigned long long fma2(unsigned long long a,
                                                   unsigned long long b,
                                                   unsigned long long c) {
    unsigned long long d;
    asm("fma.rn.f32x2 %0, %1, %2, %3;" : "=l"(d) : "l"(a), "l"(b), "l"(c));
    return d;
}

__device__ __forceinline__ unsigned long long pack_dup(float x) {
    unsigned long long r;
    unsigned u = __float_as_uint(x);
    asm("mov.b64 %0, {%1, %2};" : "=l"(r) : "r"(u), "r"(u));
    return r;
}

// ---------------------------------------------------------------------------
// K1: fused GEMM + top-2 + provisional weights.
// One token per thread; 64 experts as 32 packed f32x2 accumulators.
// W chunk in smem (broadcast LDS.128), x streamed via float4 register pipeline.
// ---------------------------------------------------------------------------
__global__ void __launch_bounds__(TPB, 2)
gemm_topk_kernel(const float* __restrict__ x, const float* __restrict__ W,
                 float* __restrict__ out_idx, float* __restrict__ out_w, int N) {
    __shared__ float4 w_s[KC * (NE / 4)];   // KC rows x 64 floats = 32 KB

    int tok = blockIdx.x * TPB + threadIdx.x;
    int tokc = (tok < N) ? tok : (N - 1);
    const float4* __restrict__ xrow =
        reinterpret_cast<const float4*>(x + (size_t)tokc * HD);

    unsigned long long acc[NE / 2];
#pragma unroll
    for (int j = 0; j < NE / 2; ++j) acc[j] = 0ull;

    // initial x prefetch: 16 floats
    float4 xa[4];
#pragma unroll
    for (int i = 0; i < 4; ++i) xa[i] = xrow[i];

    const float4* __restrict__ wg = reinterpret_cast<const float4*>(W);

    for (int c = 0; c < HD / KC; ++c) {
        __syncthreads();
        // cooperative load of W chunk: KC*64 floats = 2048 float4
#pragma unroll
        for (int i = 0; i < (KC * NE / 4) / TPB; ++i)
            w_s[threadIdx.x + i * TPB] = wg[c * KC * (NE / 4) + threadIdx.x + i * TPB];
        __syncthreads();

#pragma unroll
        for (int g = 0; g < KC / 16; ++g) {
            // prefetch next 16 x values
            float4 xb[4];
            int nextk = c * KC + (g + 1) * 16;
            if (nextk < HD) {
#pragma unroll
                for (int i = 0; i < 4; ++i) xb[i] = xrow[nextk / 4 + i];
            } else {
#pragma unroll
                for (int i = 0; i < 4; ++i) xb[i] = xa[i];
            }
            // compute 16 k-steps with xa
#pragma unroll
            for (int q = 0; q < 4; ++q) {
                float xv[4] = {xa[q].x, xa[q].y, xa[q].z, xa[q].w};
#pragma unroll
                for (int s = 0; s < 4; ++s) {
                    unsigned long long x2 = pack_dup(xv[s]);
                    int r = g * 16 + q * 4 + s;   // row within chunk
                    const ulonglong2* __restrict__ wr =
                        reinterpret_cast<const ulonglong2*>(&w_s[r * (NE / 4)]);
#pragma unroll
                    for (int j2 = 0; j2 < NE / 4; ++j2) {
                        ulonglong2 wv = wr[j2];
                        acc[2 * j2]     = fma2(x2, wv.x, acc[2 * j2]);
                        acc[2 * j2 + 1] = fma2(x2, wv.y, acc[2 * j2 + 1]);
                    }
                }
            }
#pragma unroll
            for (int i = 0; i < 4; ++i) xa[i] = xb[i];
        }
    }

    if (tok >= N) return;

    // top-2 over 64 logits (strict > : ties pick lowest index, matching lax.top_k)
    float m0 = -1e30f, m1 = -1e30f;
    int i0 = 0, i1 = 0;
#pragma unroll
    for (int j = 0; j < NE / 2; ++j) {
        float lo = __uint_as_float((unsigned)(acc[j] & 0xffffffffull));
        float hi = __uint_as_float((unsigned)(acc[j] >> 32));
        int e0 = 2 * j, e1 = 2 * j + 1;
        if (lo > m0) { m1 = m0; i1 = i0; m0 = lo; i0 = e0; }
        else if (lo > m1) { m1 = lo; i1 = e0; }
        if (hi > m0) { m1 = m0; i1 = i0; m0 = hi; i0 = e1; }
        else if (hi > m1) { m1 = hi; i1 = e1; }
    }

    // normalized top-2 weights: p_k / (p0 + p1)
    float t = expf(m1 - m0);
    float s = 1.0f / (1.0f + t);
    out_idx[2 * tok]     = (float)i0;
    out_idx[2 * tok + 1] = (float)i1;
    out_w[2 * tok]       = s;
    out_w[2 * tok + 1]   = t * s;
}

// ---------------------------------------------------------------------------
// K2: per-block expert histogram over the flat (row-major) assignment stream.
// ---------------------------------------------------------------------------
__global__ void hist_kernel(const float* __restrict__ idxf, int chunk, int flat) {
    __shared__ int h[NE];
    if (threadIdx.x < NE) h[threadIdx.x] = 0;
    __syncthreads();
    int s = blockIdx.x * chunk;
    int e = min(flat, s + chunk);
    for (int i = s + threadIdx.x; i < e; i += blockDim.x)
        atomicAdd(&h[(int)idxf[i]], 1);
    __syncthreads();
    if (threadIdx.x < NE) g_hist[blockIdx.x * NE + threadIdx.x] = h[threadIdx.x];
}

// ---------------------------------------------------------------------------
// K3: exclusive scan of block histograms per expert; counters + dropped.
// ---------------------------------------------------------------------------
__global__ void scan_kernel(float* __restrict__ out_cnt, float* __restrict__ out_drop,
                            int capacity) {
    int e = threadIdx.x;   // 64 threads
    int run = 0;
    for (int b = 0; b < NB2; ++b) {
        g_base[b * NE + e] = run;
        run += g_hist[b * NE + e];
    }
    out_cnt[e] = (float)min(run, capacity);
    __shared__ int sdrop[NE];
    sdrop[e] = max(0, run - capacity);
    __syncthreads();
    if (e == 0) {
        int tot = 0;
        for (int i = 0; i < NE; ++i) tot += sdrop[i];
        out_drop[0] = (float)tot;
    }
}

// ---------------------------------------------------------------------------
// K4: ordered capacity mask + final weight normalization.
// One warp per block; exact in-order rank via match_any within 32-wide waves.
// ---------------------------------------------------------------------------
__global__ void mask_kernel(const float* __restrict__ idxf, float* __restrict__ wf,
                            float* __restrict__ maskf, int capacity, int chunk,
                            int flat) {
    int b = blockIdx.x;
    int lane = threadIdx.x;
    __shared__ int sc[NE];
    for (int e = lane; e < NE; e += 32) sc[e] = g_base[b * NE + e];
    __syncwarp();

    int s = b * chunk;
    int e_ = min(flat, s + chunk);
    for (int i0 = s; i0 < e_; i0 += 32) {
        int i = i0 + lane;
        bool valid = (i < e_);
        unsigned am = __ballot_sync(0xffffffffu, valid);
        float m = 0.f, w = 0.f;
        if (valid) {
            int ex = (int)idxf[i];
            unsigned grp = __match_any_sync(am, ex);
            int leader = __ffs(grp) - 1;
            int prior = __popc(grp & ((1u << lane) - 1u));
            int base = 0;
            if (lane == leader) {
                base = sc[ex];
                sc[ex] = base + __popc(grp);
            }
            base = __shfl_sync(am, base, leader);
            int pos = base + prior;
            m = (pos < capacity) ? 1.f : 0.f;
            w = wf[i];
        }
        // token pair = (even,odd) lanes; chunk start is even so pairs never split
        float mo = __shfl_xor_sync(0xffffffffu, m, 1);
        if (valid) {
            float msum = m + mo;
            maskf[i] = m;
            wf[i] = w * m / (msum + 1e-10f);
        }
        __syncwarp();
    }
}

// ---------------------------------------------------------------------------
extern "C" void kernel_launch(void* const* d_in, const int* in_sizes, int n_in,
                              void* d_out, int out_size) {
    const float* x = (const float*)d_in[0];
    const float* W = (const float*)d_in[1];
    if (n_in >= 2 && in_sizes[0] < in_sizes[1]) {  // defensive input-order swap
        const float* tmp = x; x = W; W = tmp;
        int N_ = in_sizes[1] / HD; (void)N_;
    }
    int N = ((in_sizes[0] >= in_sizes[1]) ? in_sizes[0] : in_sizes[1]) / HD;
    int flat = N * TOPK;

    float* out    = (float*)d_out;
    float* f_idx  = out;
    float* f_w    = out + flat;
    float* f_mask = out + 2 * flat;
    float* f_cnt  = out + 3 * flat;
    float* f_drop = f_cnt + NE;

    int capacity = (int)(((double)N * (double)TOPK / (double)NE) * 1.25);
    int chunk = ((flat + NB2 - 1) / NB2 + 1) & ~1;  // even-aligned per-block span

    int grid1 = (N + TPB - 1) / TPB;
    gemm_topk_kernel<<<grid1, TPB>>>(x, W, f_idx, f_w, N);
    hist_kernel<<<NB2, 256>>>(f_idx, chunk, flat);
    scan_kernel<<<1, NE>>>(f_cnt, f_drop, capacity);
    mask_kernel<<<NB2, 32>>>(f_idx, f_w, f_mask, capacity, chunk, flat);
}

// round 2
// speedup vs baseline: 1.0735x; 1.0735x over previous
#include <cuda_runtime.h>
#include <math.h>

// ----------------------------------------------------------------------------
// CapacityRouter: logits = x[N,1024] @ W[1024,64]; softmax; top-2; ordered
// capacity masking (capacity = N*K/E*1.25); outputs concatenated as float32:
//   [ idx (N*2) | weights (N*2) | mask (N*2) | expert_counters (64) | dropped (1) ]
// ----------------------------------------------------------------------------

#define HD 1024
#define NE 64
#define TOPK 2
#define KC 64            // k-chunk staged in shared memory
#define TPB 256          // 8 warps: warps 0-3 experts 0-31, warps 4-7 experts 32-63
#define TOK_PER_BLK 128
#define XS_STRIDE 68     // floats; 16B-aligned rows, conflict-free LDS.128
#define MAXB 4096

__device__ int g_hist[MAXB * NE];
__device__ int g_base[MAXB * NE];
__device__ int g_edrop[NE];

__device__ __forceinline__ unsigned long long fma2(unsigned long long a,
                                                   unsigned long long b,
                                                   unsigned long long c) {
    unsigned long long d;
    asm("fma.rn.f32x2 %0, %1, %2, %3;" : "=l"(d) : "l"(a), "l"(b), "l"(c));
    return d;
}

__device__ __forceinline__ unsigned long long pack_dup(float x) {
    unsigned long long r;
    unsigned u = __float_as_uint(x);
    asm("mov.b64 %0, {%1, %2};" : "=l"(r) : "r"(u), "r"(u));
    return r;
}

// ---------------------------------------------------------------------------
// K1: fused GEMM + top-2 + weights + per-block expert histogram.
// 2 threads per token (expert-split). x staged via smem coalesced; W chunk in
// smem read warp-uniform (broadcast). 32 fp32 accumulators as 16 f32x2 regs.
// k accumulation is strictly sequential per expert (bit-stable vs round 1).
// ---------------------------------------------------------------------------
__global__ void __launch_bounds__(TPB, 3)
gemm_topk_kernel(const float* __restrict__ x, const float* __restrict__ W,
                 float* __restrict__ out_idx, float* __restrict__ out_w, int N) {
    extern __shared__ float smem[];
    float* x_s = smem;                             // 128 * 68 floats
    float* w_s = smem + TOK_PER_BLK * XS_STRIDE;   // 64 * 64 floats

    __shared__ int h[NE];

    int tid = threadIdx.x;
    int half = tid >> 7;        // expert half
    int t128 = tid & 127;       // token within block
    int tok = blockIdx.x * TOK_PER_BLK + t128;

    unsigned long long acc[16];
#pragma unroll
    for (int j = 0; j < 16; ++j) acc[j] = 0ull;

    for (int c = 0; c < HD / KC; ++c) {
        __syncthreads();
        // W chunk: KC*NE floats = 1024 float4, 4 per thread (coalesced)
        const float4* __restrict__ wg4 =
            reinterpret_cast<const float4*>(W + c * KC * NE);
        float4* ws4 = reinterpret_cast<float4*>(w_s);
#pragma unroll
        for (int i = 0; i < (KC * NE / 4) / TPB; ++i)
            ws4[tid + i * TPB] = wg4[tid + i * TPB];
        // x tile: 128 tokens x KC floats = 2048 float4, 8 per thread (coalesced)
#pragma unroll
        for (int i = 0; i < (TOK_PER_BLK * KC / 4) / TPB; ++i) {
            int idx = tid + i * TPB;
            int row = idx >> 4;            // token row 0..127
            int colv = idx & 15;           // float4 within chunk
            int grow = blockIdx.x * TOK_PER_BLK + row;
            grow = min(grow, N - 1);
            float4 v = reinterpret_cast<const float4*>(
                x + (size_t)grow * HD + c * KC)[colv];
            *reinterpret_cast<float4*>(x_s + row * XS_STRIDE + colv * 4) = v;
        }
        __syncthreads();

        const float* __restrict__ xrow = x_s + t128 * XS_STRIDE;
#pragma unroll 2
        for (int g = 0; g < KC / 4; ++g) {
            float4 xq = *reinterpret_cast<const float4*>(xrow + g * 4);
#pragma unroll
            for (int s = 0; s < 4; ++s) {
                float xv = (s == 0) ? xq.x : (s == 1) ? xq.y : (s == 2) ? xq.z : xq.w;
                unsigned long long x2 = pack_dup(xv);
                const ulonglong2* __restrict__ wr =
                    reinterpret_cast<const ulonglong2*>(
                        w_s + (g * 4 + s) * NE + half * 32);
#pragma unroll
                for (int j2 = 0; j2 < 8; ++j2) {
                    ulonglong2 wv = wr[j2];
                    acc[2 * j2]     = fma2(x2, wv.x, acc[2 * j2]);
                    acc[2 * j2 + 1] = fma2(x2, wv.y, acc[2 * j2 + 1]);
                }
            }
        }
    }

    // local top-2 over this thread's 32 experts (strict > : lowest index on tie)
    float m0 = -1e30f, m1 = -1e30f;
    int i0 = 0, i1 = 0;
#pragma unroll
    for (int j = 0; j < 16; ++j) {
        float lo = __uint_as_float((unsigned)(acc[j] & 0xffffffffull));
        float hi = __uint_as_float((unsigned)(acc[j] >> 32));
        int e0 = half * 32 + 2 * j, e1 = e0 + 1;
        if (lo > m0) { m1 = m0; i1 = i0; m0 = lo; i0 = e0; }
        else if (lo > m1) { m1 = lo; i1 = e0; }
        if (hi > m0) { m1 = m0; i1 = i0; m0 = hi; i0 = e1; }
        else if (hi > m1) { m1 = hi; i1 = e1; }
    }

    __syncthreads();   // protect x_s reuse as exchange buffer
    if (half == 1) {
        float* p = x_s + t128 * 4;
        p[0] = m0; p[1] = m1;
        p[2] = (float)i0; p[3] = (float)i1;
    }
    if (tid < NE) h[tid] = 0;
    __syncthreads();

    if (half == 0 && tok < N) {
        float bm0 = x_s[t128 * 4], bm1 = x_s[t128 * 4 + 1];
        int bi0 = (int)x_s[t128 * 4 + 2], bi1 = (int)x_s[t128 * 4 + 3];
        // merge two sorted top-2 lists; b's indices (>=32) lose ties to a's
        float f0, f1; int e0, e1;
        if (bm0 > m0) {
            f0 = bm0; e0 = bi0;
            if (bm1 > m0) { f1 = bm1; e1 = bi1; } else { f1 = m0; e1 = i0; }
        } else {
            f0 = m0; e0 = i0;
            if (bm0 > m1) { f1 = bm0; e1 = bi0; } else { f1 = m1; e1 = i1; }
        }
        float tE = expf(f1 - f0);
        float s0 = 1.0f / (1.0f + tE);
        out_idx[2 * tok]     = (float)e0;
        out_idx[2 * tok + 1] = (float)e1;
        out_w[2 * tok]       = s0;
        out_w[2 * tok + 1]   = tE * s0;
        atomicAdd(&h[e0], 1);
        atomicAdd(&h[e1], 1);
    }
    __syncthreads();
    if (tid < NE) g_hist[blockIdx.x * NE + tid] = h[tid];
}

// ---------------------------------------------------------------------------
// K2: per-expert exclusive scan across gemm blocks (one block per expert).
// ---------------------------------------------------------------------------
__global__ void scan_kernel(float* __restrict__ out_cnt, int capacity, int NB) {
    int e = blockIdx.x;     // expert
    int t = threadIdx.x;    // 256 threads
    __shared__ int ssum[256];
    int P = (NB + 255) >> 8;
    int s = t * P, eidx = min(NB, s + P);
    int sum = 0;
    for (int b = s; b < eidx; ++b) sum += g_hist[b * NE + e];
    ssum[t] = sum;
    __syncthreads();
    for (int off = 1; off < 256; off <<= 1) {
        int u = (t >= off) ? ssum[t - off] : 0;
        __syncthreads();
        ssum[t] += u;
        __syncthreads();
    }
    int run = ssum[t] - sum;   // exclusive prefix
    for (int b = s; b < eidx; ++b) {
        g_base[b * NE + e] = run;
        run += g_hist[b * NE + e];
    }
    if (t == 255) {
        int total = ssum[255];
        out_cnt[e] = (float)min(total, capacity);
        g_edrop[e] = max(0, total - capacity);
    }
}

// ---------------------------------------------------------------------------
// K3: ordered capacity mask + final weight normalization (1 warp / gemm block,
// 256 flat slots each). Block 0 also reduces the dropped count.
// ---------------------------------------------------------------------------
__global__ void mask_kernel(const float* __restrict__ idxf, float* __restrict__ wf,
                            float* __restrict__ maskf, float* __restrict__ dropf,
                            int capacity, int flat) {
    int b = blockIdx.x;
    int lane = threadIdx.x;
    if (b == 0 && lane == 0) {
        int tot = 0;
        for (int i = 0; i < NE; ++i) tot += g_edrop[i];
        dropf[0] = (float)tot;
    }
    __shared__ int sc[NE];
    for (int e = lane; e < NE; e += 32) sc[e] = g_base[b * NE + e];
    __syncwarp();

    int s = b * (TOK_PER_BLK * TOPK);
    int e_ = min(flat, s + TOK_PER_BLK * TOPK);
    for (int i0 = s; i0 < e_; i0 += 32) {
        int i = i0 + lane;
        bool valid = (i < e_);
        unsigned am = __ballot_sync(0xffffffffu, valid);
        float m = 0.f, w = 0.f;
        if (valid) {
            int ex = (int)idxf[i];
            unsigned grp = __match_any_sync(am, ex);
            int leader = __ffs(grp) - 1;
            int prior = __popc(grp & ((1u << lane) - 1u));
            int base = 0;
            if (lane == leader) {
                base = sc[ex];
                sc[ex] = base + __popc(grp);
            }
            base = __shfl_sync(am, base, leader);
            int pos = base + prior;
            m = (pos < capacity) ? 1.f : 0.f;
            w = wf[i];
        }
        float mo = __shfl_xor_sync(0xffffffffu, m, 1);  // token pair partner
        if (valid) {
            float msum = m + mo;
            maskf[i] = m;
            wf[i] = w * m / (msum + 1e-10f);
        }
        __syncwarp();
    }
}

// ---------------------------------------------------------------------------
extern "C" void kernel_launch(void* const* d_in, const int* in_sizes, int n_in,
                              void* d_out, int out_size) {
    const float* x = (const float*)d_in[0];
    const float* W = (const float*)d_in[1];
    if (n_in >= 2 && in_sizes[0] < in_sizes[1]) {   // defensive input-order swap
        const float* tmp = x; x = W; W = tmp;
    }
    int N = ((in_sizes[0] >= in_sizes[1]) ? in_sizes[0] : in_sizes[1]) / HD;
    int flat = N * TOPK;
    int NB = (N + TOK_PER_BLK - 1) / TOK_PER_BLK;

    float* out    = (float*)d_out;
    float* f_idx  = out;
    float* f_w    = out + flat;
    float* f_mask = out + 2 * flat;
    float* f_cnt  = out + 3 * flat;
    float* f_drop = f_cnt + NE;

    int capacity = (int)(((double)N * (double)TOPK / (double)NE) * 1.25);

    int smem_bytes = (TOK_PER_BLK * XS_STRIDE + KC * NE) * 4;   // 51200 B
    cudaFuncSetAttribute(gemm_topk_kernel,
                         cudaFuncAttributeMaxDynamicSharedMemorySize, smem_bytes);

    gemm_topk_kernel<<<NB, TPB, smem_bytes>>>(x, W, f_idx, f_w, N);
    scan_kernel<<<NE, 256>>>(f_cnt, capacity, NB);
    mask_kernel<<<NB, 32>>>(f_idx, f_w, f_mask, f_drop, capacity, flat);
}

// round 3
// speedup vs baseline: 1.6083x; 1.4982x over previous
#include <cuda_runtime.h>
#include <math.h>

// ----------------------------------------------------------------------------
// CapacityRouter: logits = x[N,1024] @ W[1024,64]; softmax; top-2; ordered
// capacity masking (capacity = N*K/E*1.25); outputs concatenated as float32:
//   [ idx (N*2) | weights (N*2) | mask (N*2) | expert_counters (64) | dropped (1) ]
// ----------------------------------------------------------------------------

#define HD 1024
#define NE 64
#define TOPK 2
#define KC 64            // k-chunk staged in shared memory
#define TPB 256
#define TOKB 256         // tokens per block
#define XS 65            // x_s row stride (odd -> conflict-free LDS.32 reads)
#define MAXB 4096

__device__ int g_hist[MAXB * NE];
__device__ int g_base[MAXB * NE];
__device__ int g_edrop[NE];

__device__ __forceinline__ unsigned long long fma2(unsigned long long a,
                                                   unsigned long long b,
                                                   unsigned long long c) {
    unsigned long long d;
    asm("fma.rn.f32x2 %0, %1, %2, %3;" : "=l"(d) : "l"(a), "l"(b), "l"(c));
    return d;
}

__device__ __forceinline__ unsigned long long pack_dup(float x) {
    unsigned long long r;
    unsigned u = __float_as_uint(x);
    asm("mov.b64 %0, {%1, %2};" : "=l"(r) : "r"(u), "r"(u));
    return r;
}

// ---------------------------------------------------------------------------
// K1: fused GEMM + top-2 + weights + per-block expert histogram.
// Thread = 4 tokens x 16 experts (64 fp32 accumulators as 32 f32x2).
// eg = tid>>6 (expert group, warp-uniform -> W LDS broadcast);
// ts = tid&63; tokens = ts + 64*t. Per k-step: 4 LDS.128 (W, broadcast)
// + 4 LDS.32 (x, conflict-free) + 32 FFMA2.
// k accumulation strictly sequential per (token, expert) -> bit-stable.
// ---------------------------------------------------------------------------
__global__ void __launch_bounds__(TPB, 2)
gemm_topk_kernel(const float* __restrict__ x, const float* __restrict__ W,
                 float* __restrict__ out_idx, float* __restrict__ out_w, int N) {
    extern __shared__ float smem[];
    float* x_s = smem;                 // TOKB * XS floats = 66560 B
    float* w_s = smem + TOKB * XS;     // KC * NE floats  = 16384 B

    __shared__ int h[NE];

    int tid = threadIdx.x;
    int eg = tid >> 6;     // expert group 0..3 (experts eg*16 .. eg*16+15)
    int ts = tid & 63;     // token slot; tokens ts + 64*t, t=0..3

    unsigned long long acc[32];        // [t][j]: t*8+j
#pragma unroll
    for (int j = 0; j < 32; ++j) acc[j] = 0ull;

    const float4* __restrict__ wg4 = reinterpret_cast<const float4*>(W);

    for (int c = 0; c < HD / KC; ++c) {
        __syncthreads();
        // W chunk: KC*NE = 4096 floats = 1024 float4; 4 per thread, coalesced
        float4* ws4 = reinterpret_cast<float4*>(w_s);
#pragma unroll
        for (int i = 0; i < (KC * NE / 4) / TPB; ++i)
            ws4[tid + i * TPB] = wg4[c * (KC * NE / 4) + tid + i * TPB];
        // x tile: TOKB tokens x KC floats = 4096 float4; 16 per thread.
        // idx -> token = idx>>4, kq = idx&15 (16 consecutive float4 per row
        // across 16 lanes -> 256B coalesced segments).
#pragma unroll
        for (int i = 0; i < (TOKB * KC / 4) / TPB; ++i) {
            int idx = tid + i * TPB;
            int row = idx >> 4;
            int kq = idx & 15;
            int grow = blockIdx.x * TOKB + row;
            grow = min(grow, N - 1);
            float4 v = reinterpret_cast<const float4*>(
                x + (size_t)grow * HD + c * KC)[kq];
            float* p = x_s + row * XS + kq * 4;
            p[0] = v.x; p[1] = v.y; p[2] = v.z; p[3] = v.w;
        }
        __syncthreads();

        const float* __restrict__ x0 = x_s + ts * XS;
#pragma unroll 4
        for (int k = 0; k < KC; ++k) {
            // W for this k: 16 experts = 8 f32x2, warp-uniform address
            const ulonglong2* __restrict__ wr =
                reinterpret_cast<const ulonglong2*>(w_s + k * NE + eg * 16);
            ulonglong2 w0 = wr[0], w1 = wr[1], w2 = wr[2], w3 = wr[3];
            // x for 4 tokens, conflict-free (odd stride)
            unsigned long long xt0 = pack_dup(x0[k]);
            unsigned long long xt1 = pack_dup(x0[64 * XS + k]);
            unsigned long long xt2 = pack_dup(x0[128 * XS + k]);
            unsigned long long xt3 = pack_dup(x0[192 * XS + k]);
            acc[0]  = fma2(xt0, w0.x, acc[0]);
            acc[1]  = fma2(xt0, w0.y, acc[1]);
            acc[2]  = fma2(xt0, w1.x, acc[2]);
            acc[3]  = fma2(xt0, w1.y, acc[3]);
            acc[4]  = fma2(xt0, w2.x, acc[4]);
            acc[5]  = fma2(xt0, w2.y, acc[5]);
            acc[6]  = fma2(xt0, w3.x, acc[6]);
            acc[7]  = fma2(xt0, w3.y, acc[7]);
            acc[8]  = fma2(xt1, w0.x, acc[8]);
            acc[9]  = fma2(xt1, w0.y, acc[9]);
            acc[10] = fma2(xt1, w1.x, acc[10]);
            acc[11] = fma2(xt1, w1.y, acc[11]);
            acc[12] = fma2(xt1, w2.x, acc[12]);
            acc[13] = fma2(xt1, w2.y, acc[13]);
            acc[14] = fma2(xt1, w3.x, acc[14]);
            acc[15] = fma2(xt1, w3.y, acc[15]);
            acc[16] = fma2(xt2, w0.x, acc[16]);
            acc[17] = fma2(xt2, w0.y, acc[17]);
            acc[18] = fma2(xt2, w1.x, acc[18]);
            acc[19] = fma2(xt2, w1.y, acc[19]);
            acc[20] = fma2(xt2, w2.x, acc[20]);
            acc[21] = fma2(xt2, w2.y, acc[21]);
            acc[22] = fma2(xt2, w3.x, acc[22]);
            acc[23] = fma2(xt2, w3.y, acc[23]);
            acc[24] = fma2(xt3, w0.x, acc[24]);
            acc[25] = fma2(xt3, w0.y, acc[25]);
            acc[26] = fma2(xt3, w1.x, acc[26]);
            acc[27] = fma2(xt3, w1.y, acc[27]);
            acc[28] = fma2(xt3, w2.x, acc[28]);
            acc[29] = fma2(xt3, w2.y, acc[29]);
            acc[30] = fma2(xt3, w3.x, acc[30]);
            acc[31] = fma2(xt3, w3.y, acc[31]);
        }
    }

    // per-(token, eg) top-2 over 16 experts, ascending, strict >
    __syncthreads();               // x_s reuse as exchange buffer
    float* xch = x_s;              // [token][eg][4] : 256*16 floats
#pragma unroll
    for (int t = 0; t < 4; ++t) {
        float m0 = -1e30f, m1 = -1e30f;
        int i0 = 0, i1 = 0;
#pragma unroll
        for (int j = 0; j < 8; ++j) {
            unsigned long long a = acc[t * 8 + j];
            float lo = __uint_as_float((unsigned)(a & 0xffffffffull));
            float hi = __uint_as_float((unsigned)(a >> 32));
            int e0 = eg * 16 + 2 * j, e1 = e0 + 1;
            if (lo > m0) { m1 = m0; i1 = i0; m0 = lo; i0 = e0; }
            else if (lo > m1) { m1 = lo; i1 = e0; }
            if (hi > m0) { m1 = m0; i1 = i0; m0 = hi; i0 = e1; }
            else if (hi > m1) { m1 = hi; i1 = e1; }
        }
        float* p = xch + ((ts + 64 * t) * 16 + eg * 4);
        p[0] = m0; p[1] = m1; p[2] = (float)i0; p[3] = (float)i1;
    }
    if (tid < NE) h[tid] = 0;
    __syncthreads();

    // thread tid finalizes token tid: merge 4 groups in ascending-eg order
    {
        int tok = blockIdx.x * TOKB + tid;
        const float* p0 = xch + tid * 16;
        float m0 = p0[0], m1 = p0[1];
        int i0 = (int)p0[2], i1 = (int)p0[3];
#pragma unroll
        for (int g = 1; g < 4; ++g) {
            const float* p = xch + tid * 16 + g * 4;
            float b0 = p[0], b1 = p[1];
            int jb0 = (int)p[2], jb1 = (int)p[3];
            if (b0 > m0) {
                if (b1 > m0) { m0 = b0; i0 = jb0; m1 = b1; i1 = jb1; }
                else { m1 = m0; i1 = i0; m0 = b0; i0 = jb0; }
            } else if (b0 > m1) { m1 = b0; i1 = jb0; }
        }
        if (tok < N) {
            float tE = expf(m1 - m0);
            float s0 = 1.0f / (1.0f + tE);
            out_idx[2 * tok]     = (float)i0;
            out_idx[2 * tok + 1] = (float)i1;
            out_w[2 * tok]       = s0;
            out_w[2 * tok + 1]   = tE * s0;
            atomicAdd(&h[i0], 1);
            atomicAdd(&h[i1], 1);
        }
    }
    __syncthreads();
    if (tid < NE) g_hist[blockIdx.x * NE + tid] = h[tid];
}

// ---------------------------------------------------------------------------
// K2: per-expert exclusive scan across gemm blocks (one block per expert).
// ---------------------------------------------------------------------------
__global__ void scan_kernel(float* __restrict__ out_cnt, int capacity, int NB) {
    int e = blockIdx.x;
    int t = threadIdx.x;     // 256
    __shared__ int ssum[256];
    int P = (NB + 255) >> 8;
    int s = t * P, eidx = min(NB, s + P);
    int sum = 0;
    for (int b = s; b < eidx; ++b) sum += g_hist[b * NE + e];
    ssum[t] = sum;
    __syncthreads();
    for (int off = 1; off < 256; off <<= 1) {
        int u = (t >= off) ? ssum[t - off] : 0;
        __syncthreads();
        ssum[t] += u;
        __syncthreads();
    }
    int run = ssum[t] - sum;
    for (int b = s; b < eidx; ++b) {
        g_base[b * NE + e] = run;
        run += g_hist[b * NE + e];
    }
    if (t == 255) {
        int total = ssum[255];
        out_cnt[e] = (float)min(total, capacity);
        g_edrop[e] = max(0, total - capacity);
    }
}

// ---------------------------------------------------------------------------
// K3: ordered capacity mask + final weight normalization.
// One warp per gemm block (512 flat slots). Block 0 reduces dropped count.
// ---------------------------------------------------------------------------
__global__ void mask_kernel(const float* __restrict__ idxf, float* __restrict__ wf,
                            float* __restrict__ maskf, float* __restrict__ dropf,
                            int capacity, int flat) {
    int b = blockIdx.x;
    int lane = threadIdx.x;
    if (b == 0 && lane == 0) {
        int tot = 0;
        for (int i = 0; i < NE; ++i) tot += g_edrop[i];
        dropf[0] = (float)tot;
    }
    __shared__ int sc[NE];
    for (int e = lane; e < NE; e += 32) sc[e] = g_base[b * NE + e];
    __syncwarp();

    int s = b * (TOKB * TOPK);
    int e_ = min(flat, s + TOKB * TOPK);
    for (int i0 = s; i0 < e_; i0 += 32) {
        int i = i0 + lane;
        bool valid = (i < e_);
        unsigned am = __ballot_sync(0xffffffffu, valid);
        float m = 0.f, w = 0.f;
        if (valid) {
            int ex = (int)idxf[i];
            unsigned grp = __match_any_sync(am, ex);
            int leader = __ffs(grp) - 1;
            int prior = __popc(grp & ((1u << lane) - 1u));
            int base = 0;
            if (lane == leader) {
                base = sc[ex];
                sc[ex] = base + __popc(grp);
            }
            base = __shfl_sync(am, base, leader);
            int pos = base + prior;
            m = (pos < capacity) ? 1.f : 0.f;
            w = wf[i];
        }
        float mo = __shfl_xor_sync(0xffffffffu, m, 1);
        if (valid) {
            float msum = m + mo;
            maskf[i] = m;
            wf[i] = w * m / (msum + 1e-10f);
        }
        __syncwarp();
    }
}

// ---------------------------------------------------------------------------
extern "C" void kernel_launch(void* const* d_in, const int* in_sizes, int n_in,
                              void* d_out, int out_size) {
    const float* x = (const float*)d_in[0];
    const float* W = (const float*)d_in[1];
    if (n_in >= 2 && in_sizes[0] < in_sizes[1]) {
        const float* tmp = x; x = W; W = tmp;
    }
    int N = ((in_sizes[0] >= in_sizes[1]) ? in_sizes[0] : in_sizes[1]) / HD;
    int flat = N * TOPK;
    int NB = (N + TOKB - 1) / TOKB;

    float* out    = (float*)d_out;
    float* f_idx  = out;
    float* f_w    = out + flat;
    float* f_mask = out + 2 * flat;
    float* f_cnt  = out + 3 * flat;
    float* f_drop = f_cnt + NE;

    int capacity = (int)(((double)N * (double)TOPK / (double)NE) * 1.25);

    int smem_bytes = (TOKB * XS + KC * NE) * 4;   // 82944 B
    cudaFuncSetAttribute(gemm_topk_kernel,
                         cudaFuncAttributeMaxDynamicSharedMemorySize, smem_bytes);

    gemm_topk_kernel<<<NB, TPB, smem_bytes>>>(x, W, f_idx, f_w, N);
    scan_kernel<<<NE, 256>>>(f_cnt, capacity, NB);
    mask_kernel<<<NB, 32>>>(f_idx, f_w, f_mask, f_drop, capacity, flat);
}

// round 4
// speedup vs baseline: 1.6272x; 1.0118x over previous
#include <cuda_runtime.h>
#include <math.h>

// ----------------------------------------------------------------------------
// CapacityRouter: logits = x[N,1024] @ W[1024,64]; softmax; top-2; ordered
// capacity masking (capacity = N*K/E*1.25); outputs concatenated as float32:
//   [ idx (N*2) | weights (N*2) | mask (N*2) | expert_counters (64) | dropped (1) ]
// ----------------------------------------------------------------------------

#define HD 1024
#define NE 64
#define TOPK 2
#define KC 32            // k-chunk
#define TPB 256
#define TOKB 128         // tokens per block
#define XST 129          // x_s k-major row stride (floats): conflict-free ld+st
#define MAXB 4096

__device__ int g_hist[MAXB * NE];
__device__ int g_base[MAXB * NE];
__device__ int g_edrop[NE];

__device__ __forceinline__ unsigned long long fma2(unsigned long long a,
                                                   unsigned long long b,
                                                   unsigned long long c) {
    unsigned long long d;
    asm("fma.rn.f32x2 %0, %1, %2, %3;" : "=l"(d) : "l"(a), "l"(b), "l"(c));
    return d;
}

__device__ __forceinline__ unsigned long long pack_dup(float x) {
    unsigned long long r;
    unsigned u = __float_as_uint(x);
    asm("mov.b64 %0, {%1, %2};" : "=l"(r) : "r"(u), "r"(u));
    return r;
}

__device__ __forceinline__ void cp_async16(float* smem_dst, const float* gmem_src) {
    unsigned s = (unsigned)__cvta_generic_to_shared(smem_dst);
    asm volatile("cp.async.ca.shared.global [%0], [%1], 16;\n"
                 :: "r"(s), "l"(gmem_src));
}
#define CP_COMMIT() asm volatile("cp.async.commit_group;\n" ::: "memory")
#define CP_WAIT0()  asm volatile("cp.async.wait_group 0;\n" ::: "memory")

// ---------------------------------------------------------------------------
// K1: fused GEMM + top-2 + weights + per-block expert histogram.
// Thread = 2 tokens x 16 experts (32 fp32 acc as 16 f32x2). eg = tid>>6
// (warp-uniform -> W LDS broadcast), ts = tid&63, tokens = ts, ts+64.
// Double-buffered: W staged via cp.async a chunk ahead; x LDG'd into regs
// during previous chunk's compute, transposed to k-major smem (stride 129).
// k accumulation strictly sequential per (token, expert) -> bit-stable.
// ---------------------------------------------------------------------------
__global__ void __launch_bounds__(TPB, 3)
gemm_topk_kernel(const float* __restrict__ x, const float* __restrict__ W,
                 float* __restrict__ out_idx, float* __restrict__ out_w, int N) {
    extern __shared__ float smem[];
    float* x_s = smem;                    // 2 * KC * XST floats
    float* w_s = smem + 2 * KC * XST;     // 2 * KC * NE floats
    __shared__ int h[NE];

    const int tid = threadIdx.x;
    const int eg = tid >> 6;      // expert group 0..3 (experts eg*16..+15)
    const int ts = tid & 63;      // token slot; tokens ts, ts+64
    const int NC = HD / KC;       // 32 chunks

    // staging mapping: idx = tid + i*TPB -> row = idx>>3, kq = idx&7
    const int srow = tid >> 3;    // 0..31 ; rows srow + 32*i
    const int skq = tid & 7;      // float4 within chunk

    unsigned long long acc[16];   // [t][j] = t*8+j
#pragma unroll
    for (int j = 0; j < 16; ++j) acc[j] = 0ull;

    // clamped global rows for the 4 staged tokens
    int grows[4];
#pragma unroll
    for (int i = 0; i < 4; ++i)
        grows[i] = min(blockIdx.x * TOKB + srow + 32 * i, N - 1);

    // prologue: chunk 0
    float4 xr[4];
#pragma unroll
    for (int i = 0; i < 4; ++i)
        xr[i] = *reinterpret_cast<const float4*>(
            x + (size_t)grows[i] * HD + skq * 4);
#pragma unroll
    for (int i = 0; i < 2; ++i)
        cp_async16(w_s + (tid + i * TPB) * 4, W + (tid + i * TPB) * 4);
    CP_COMMIT();

    for (int c = 0; c < NC; ++c) {
        const int b = c & 1;
        float* xb = x_s + b * KC * XST;
        float* wb = w_s + b * KC * NE;

        // store staged x (chunk c) into k-major smem: 16 conflict-free STS.32
#pragma unroll
        for (int i = 0; i < 4; ++i) {
            int row = srow + 32 * i;
            xb[(skq * 4 + 0) * XST + row] = xr[i].x;
            xb[(skq * 4 + 1) * XST + row] = xr[i].y;
            xb[(skq * 4 + 2) * XST + row] = xr[i].z;
            xb[(skq * 4 + 3) * XST + row] = xr[i].w;
        }
        CP_WAIT0();            // W chunk c landed
        __syncthreads();

        // prefetch chunk c+1
        if (c + 1 < NC) {
#pragma unroll
            for (int i = 0; i < 4; ++i)
                xr[i] = *reinterpret_cast<const float4*>(
                    x + (size_t)grows[i] * HD + (c + 1) * KC + skq * 4);
            float* wnb = w_s + (1 - b) * KC * NE;
            const float* wsrc = W + (c + 1) * KC * NE;
#pragma unroll
            for (int i = 0; i < 2; ++i)
                cp_async16(wnb + (tid + i * TPB) * 4, wsrc + (tid + i * TPB) * 4);
            CP_COMMIT();
        }

        // compute chunk c
        const float* xrow = xb + ts;
#pragma unroll 8
        for (int k = 0; k < KC; ++k) {
            const ulonglong2* __restrict__ wr =
                reinterpret_cast<const ulonglong2*>(wb + k * NE + eg * 16);
            ulonglong2 w0 = wr[0], w1 = wr[1], w2 = wr[2], w3 = wr[3];
            unsigned long long xt0 = pack_dup(xrow[k * XST]);
            unsigned long long xt1 = pack_dup(xrow[k * XST + 64]);
            acc[0]  = fma2(xt0, w0.x, acc[0]);
            acc[1]  = fma2(xt0, w0.y, acc[1]);
            acc[2]  = fma2(xt0, w1.x, acc[2]);
            acc[3]  = fma2(xt0, w1.y, acc[3]);
            acc[4]  = fma2(xt0, w2.x, acc[4]);
            acc[5]  = fma2(xt0, w2.y, acc[5]);
            acc[6]  = fma2(xt0, w3.x, acc[6]);
            acc[7]  = fma2(xt0, w3.y, acc[7]);
            acc[8]  = fma2(xt1, w0.x, acc[8]);
            acc[9]  = fma2(xt1, w0.y, acc[9]);
            acc[10] = fma2(xt1, w1.x, acc[10]);
            acc[11] = fma2(xt1, w1.y, acc[11]);
            acc[12] = fma2(xt1, w2.x, acc[12]);
            acc[13] = fma2(xt1, w2.y, acc[13]);
            acc[14] = fma2(xt1, w3.x, acc[14]);
            acc[15] = fma2(xt1, w3.y, acc[15]);
        }
        __syncthreads();
    }

    // per-(token, eg) top-2 over 16 experts (ascending, strict >)
    float* xch = x_s;     // reuse: [token][eg][4] = 128*16 floats
#pragma unroll
    for (int t = 0; t < 2; ++t) {
        float m0 = -1e30f, m1 = -1e30f;
        int i0 = 0, i1 = 0;
#pragma unroll
        for (int j = 0; j < 8; ++j) {
            unsigned long long a = acc[t * 8 + j];
            float lo = __uint_as_float((unsigned)(a & 0xffffffffull));
            float hi = __uint_as_float((unsigned)(a >> 32));
            int e0 = eg * 16 + 2 * j, e1 = e0 + 1;
            if (lo > m0) { m1 = m0; i1 = i0; m0 = lo; i0 = e0; }
            else if (lo > m1) { m1 = lo; i1 = e0; }
            if (hi > m0) { m1 = m0; i1 = i0; m0 = hi; i0 = e1; }
            else if (hi > m1) { m1 = hi; i1 = e1; }
        }
        float* p = xch + ((ts + 64 * t) * 16 + eg * 4);
        p[0] = m0; p[1] = m1; p[2] = (float)i0; p[3] = (float)i1;
    }
    if (tid < NE) h[tid] = 0;
    __syncthreads();

    // threads 0..127 finalize one token each: merge 4 groups ascending
    if (tid < TOKB) {
        int tok = blockIdx.x * TOKB + tid;
        const float* p0 = xch + tid * 16;
        float m0 = p0[0], m1 = p0[1];
        int i0 = (int)p0[2], i1 = (int)p0[3];
#pragma unroll
        for (int g = 1; g < 4; ++g) {
            const float* p = xch + tid * 16 + g * 4;
            float b0 = p[0], b1 = p[1];
            int jb0 = (int)p[2], jb1 = (int)p[3];
            if (b0 > m0) {
                if (b1 > m0) { m0 = b0; i0 = jb0; m1 = b1; i1 = jb1; }
                else { m1 = m0; i1 = i0; m0 = b0; i0 = jb0; }
            } else if (b0 > m1) { m1 = b0; i1 = jb0; }
        }
        if (tok < N) {
            float tE = expf(m1 - m0);
            float s0 = 1.0f / (1.0f + tE);
            out_idx[2 * tok]     = (float)i0;
            out_idx[2 * tok + 1] = (float)i1;
            out_w[2 * tok]       = s0;
            out_w[2 * tok + 1]   = tE * s0;
            atomicAdd(&h[i0], 1);
            atomicAdd(&h[i1], 1);
        }
    }
    __syncthreads();
    if (tid < NE) g_hist[blockIdx.x * NE + tid] = h[tid];
}

// ---------------------------------------------------------------------------
// K2: per-expert exclusive scan across gemm blocks (one block per expert).
// ---------------------------------------------------------------------------
__global__ void scan_kernel(float* __restrict__ out_cnt, int capacity, int NB) {
    int e = blockIdx.x;
    int t = threadIdx.x;     // 256
    __shared__ int ssum[256];
    int P = (NB + 255) >> 8;
    int s = t * P, eidx = min(NB, s + P);
    int sum = 0;
    for (int b = s; b < eidx; ++b) sum += g_hist[b * NE + e];
    ssum[t] = sum;
    __syncthreads();
    for (int off = 1; off < 256; off <<= 1) {
        int u = (t >= off) ? ssum[t - off] : 0;
        __syncthreads();
        ssum[t] += u;
        __syncthreads();
    }
    int run = ssum[t] - sum;
    for (int b = s; b < eidx; ++b) {
        g_base[b * NE + e] = run;
        run += g_hist[b * NE + e];
    }
    if (t == 255) {
        int total = ssum[255];
        out_cnt[e] = (float)min(total, capacity);
        g_edrop[e] = max(0, total - capacity);
    }
}

// ---------------------------------------------------------------------------
// K3: ordered capacity mask + final weight normalization.
// One warp per gemm block (256 flat slots). Block 0 reduces dropped count.
// ---------------------------------------------------------------------------
__global__ void mask_kernel(const float* __restrict__ idxf, float* __restrict__ wf,
                            float* __restrict__ maskf, float* __restrict__ dropf,
                            int capacity, int flat) {
    int b = blockIdx.x;
    int lane = threadIdx.x;
    if (b == 0 && lane == 0) {
        int tot = 0;
        for (int i = 0; i < NE; ++i) tot += g_edrop[i];
        dropf[0] = (float)tot;
    }
    __shared__ int sc[NE];
    for (int e = lane; e < NE; e += 32) sc[e] = g_base[b * NE + e];
    __syncwarp();

    int s = b * (TOKB * TOPK);
    int e_ = min(flat, s + TOKB * TOPK);
    for (int i0 = s; i0 < e_; i0 += 32) {
        int i = i0 + lane;
        bool valid = (i < e_);
        unsigned am = __ballot_sync(0xffffffffu, valid);
        float m = 0.f, w = 0.f;
        if (valid) {
            int ex = (int)idxf[i];
            unsigned grp = __match_any_sync(am, ex);
            int leader = __ffs(grp) - 1;
            int prior = __popc(grp & ((1u << lane) - 1u));
            int base = 0;
            if (lane == leader) {
                base = sc[ex];
                sc[ex] = base + __popc(grp);
            }
            base = __shfl_sync(am, base, leader);
            int pos = base + prior;
            m = (pos < capacity) ? 1.f : 0.f;
            w = wf[i];
        }
        float mo = __shfl_xor_sync(0xffffffffu, m, 1);
        if (valid) {
            float msum = m + mo;
            maskf[i] = m;
            wf[i] = w * m / (msum + 1e-10f);
        }
        __syncwarp();
    }
}

// ---------------------------------------------------------------------------
extern "C" void kernel_launch(void* const* d_in, const int* in_sizes, int n_in,
                              void* d_out, int out_size) {
    const float* x = (const float*)d_in[0];
    const float* W = (const float*)d_in[1];
    if (n_in >= 2 && in_sizes[0] < in_sizes[1]) {
        const float* tmp = x; x = W; W = tmp;
    }
    int N = ((in_sizes[0] >= in_sizes[1]) ? in_sizes[0] : in_sizes[1]) / HD;
    int flat = N * TOPK;
    int NB = (N + TOKB - 1) / TOKB;

    float* out    = (float*)d_out;
    float* f_idx  = out;
    float* f_w    = out + flat;
    float* f_mask = out + 2 * flat;
    float* f_cnt  = out + 3 * flat;
    float* f_drop = f_cnt + NE;

    int capacity = (int)(((double)N * (double)TOPK / (double)NE) * 1.25);

    int smem_bytes = (2 * KC * XST + 2 * KC * NE) * 4;   // 49408 B
    cudaFuncSetAttribute(gemm_topk_kernel,
                         cudaFuncAttributeMaxDynamicSharedMemorySize, smem_bytes);

    gemm_topk_kernel<<<NB, TPB, smem_bytes>>>(x, W, f_idx, f_w, N);
    scan_kernel<<<NE, 256>>>(f_cnt, capacity, NB);
    mask_kernel<<<NB, 32>>>(f_idx, f_w, f_mask, f_drop, capacity, flat);
}

// round 5
// speedup vs baseline: 1.7733x; 1.0897x over previous
#include <cuda_runtime.h>
#include <math.h>

// ----------------------------------------------------------------------------
// CapacityRouter: logits = x[N,1024] @ W[1024,64]; softmax; top-2; ordered
// capacity masking (capacity = N*K/E*1.25); outputs concatenated as float32:
//   [ idx (N*2) | weights (N*2) | mask (N*2) | expert_counters (64) | dropped (1) ]
// ----------------------------------------------------------------------------

#define HD 1024
#define NE 64
#define TOPK 2
#define KC 16            // k-chunk
#define TPB 128          // warp = expert group (16 experts)
#define TOKB 96          // tokens per block (3 per thread: ts, ts+32, ts+64)
#define XSS 20           // x_s row stride in floats (80B: 16B-aligned)
#define MAXB 4096

__device__ int g_hist[MAXB * NE];
__device__ int g_base[MAXB * NE];
__device__ int g_edrop[NE];

__device__ __forceinline__ unsigned long long fma2(unsigned long long a,
                                                   unsigned long long b,
                                                   unsigned long long c) {
    unsigned long long d;
    asm("fma.rn.f32x2 %0, %1, %2, %3;" : "=l"(d) : "l"(a), "l"(b), "l"(c));
    return d;
}

__device__ __forceinline__ unsigned long long pack_dup(float x) {
    unsigned long long r;
    unsigned u = __float_as_uint(x);
    asm("mov.b64 %0, {%1, %2};" : "=l"(r) : "r"(u), "r"(u));
    return r;
}

__device__ __forceinline__ void cp_async16(float* smem_dst, const float* gmem_src) {
    unsigned s = (unsigned)__cvta_generic_to_shared(smem_dst);
    asm volatile("cp.async.ca.shared.global [%0], [%1], 16;\n"
                 :: "r"(s), "l"(gmem_src));
}
#define CP_COMMIT() asm volatile("cp.async.commit_group;\n" ::: "memory")
#define CP_WAIT0()  asm volatile("cp.async.wait_group 0;\n" ::: "memory")

// ---------------------------------------------------------------------------
// K1: fused GEMM + top-2 + weights + per-block expert histogram.
// Thread = 3 tokens x 16 experts (48 fp32 acc as 24 f32x2). Warp = expert
// group eg = tid>>5 (W LDS fully warp-uniform -> broadcast). x and W both
// staged via double-buffered cp.async; x row-major stride 20 (reads hit the
// 512B crossbar floor). k accumulation strictly sequential -> bit-stable.
// ---------------------------------------------------------------------------
__global__ void __launch_bounds__(TPB, 6)
gemm_topk_kernel(const float* __restrict__ x, const float* __restrict__ W,
                 float* __restrict__ out_idx, float* __restrict__ out_w, int N) {
    extern __shared__ float smem[];
    float* x_s = smem;                      // 2 * TOKB * XSS floats
    float* w_s = smem + 2 * TOKB * XSS;     // 2 * KC * NE floats
    __shared__ int h[NE];

    const int tid = threadIdx.x;
    const int eg = tid >> 5;      // expert group 0..3 (experts eg*16..+15)
    const int ts = tid & 31;      // lane; tokens ts, ts+32, ts+64
    const int NC = HD / KC;       // 64 chunks

    // staging: x rows r0, r0+32, r0+64 (kq-th float4); W 2 float4
    const int r0 = tid >> 2;      // 0..31
    const int kq = tid & 3;

    int grows[3];
#pragma unroll
    for (int i = 0; i < 3; ++i)
        grows[i] = min(blockIdx.x * TOKB + r0 + 32 * i, N - 1);

    unsigned long long acc[24];   // [t][j] = t*8 + j
#pragma unroll
    for (int j = 0; j < 24; ++j) acc[j] = 0ull;

    // prologue: stage chunk 0 into buffer 0
#pragma unroll
    for (int i = 0; i < 3; ++i)
        cp_async16(x_s + (r0 + 32 * i) * XSS + kq * 4,
                   x + (size_t)grows[i] * HD + kq * 4);
#pragma unroll
    for (int i = 0; i < 2; ++i)
        cp_async16(w_s + (tid + i * TPB) * 4, W + (tid + i * TPB) * 4);
    CP_COMMIT();

    for (int c = 0; c < NC; ++c) {
        const int b = c & 1;
        CP_WAIT0();               // chunk c landed (this thread's pieces)
        __syncthreads();          // all threads' pieces; prev compute done

        if (c + 1 < NC) {         // prefetch chunk c+1 into buffer b^1
            float* xnb = x_s + (1 - b) * TOKB * XSS;
            float* wnb = w_s + (1 - b) * KC * NE;
            const float* xsrc = x + (size_t)(c + 1) * KC;
#pragma unroll
            for (int i = 0; i < 3; ++i)
                cp_async16(xnb + (r0 + 32 * i) * XSS + kq * 4,
                           xsrc + (size_t)grows[i] * HD + kq * 4);
            const float* wsrc = W + (c + 1) * KC * NE;
#pragma unroll
            for (int i = 0; i < 2; ++i)
                cp_async16(wnb + (tid + i * TPB) * 4, wsrc + (tid + i * TPB) * 4);
            CP_COMMIT();
        }

        // compute chunk c from buffer b
        const float* xb = x_s + b * TOKB * XSS;
        const float* wb = w_s + b * KC * NE;
#pragma unroll
        for (int kg = 0; kg < KC / 4; ++kg) {
            float4 xq0 = *reinterpret_cast<const float4*>(xb + ts * XSS + kg * 4);
            float4 xq1 = *reinterpret_cast<const float4*>(xb + (ts + 32) * XSS + kg * 4);
            float4 xq2 = *reinterpret_cast<const float4*>(xb + (ts + 64) * XSS + kg * 4);
#pragma unroll
            for (int kk = 0; kk < 4; ++kk) {
                int k = kg * 4 + kk;
                float v0 = (kk == 0) ? xq0.x : (kk == 1) ? xq0.y : (kk == 2) ? xq0.z : xq0.w;
                float v1 = (kk == 0) ? xq1.x : (kk == 1) ? xq1.y : (kk == 2) ? xq1.z : xq1.w;
                float v2 = (kk == 0) ? xq2.x : (kk == 1) ? xq2.y : (kk == 2) ? xq2.z : xq2.w;
                unsigned long long xt0 = pack_dup(v0);
                unsigned long long xt1 = pack_dup(v1);
                unsigned long long xt2 = pack_dup(v2);
                const ulonglong2* __restrict__ wr =
                    reinterpret_cast<const ulonglong2*>(wb + k * NE + eg * 16);
                ulonglong2 wa = wr[0], wbb = wr[1], wc = wr[2], wd = wr[3];
                acc[0]  = fma2(xt0, wa.x,  acc[0]);
                acc[1]  = fma2(xt0, wa.y,  acc[1]);
                acc[2]  = fma2(xt0, wbb.x, acc[2]);
                acc[3]  = fma2(xt0, wbb.y, acc[3]);
                acc[4]  = fma2(xt0, wc.x,  acc[4]);
                acc[5]  = fma2(xt0, wc.y,  acc[5]);
                acc[6]  = fma2(xt0, wd.x,  acc[6]);
                acc[7]  = fma2(xt0, wd.y,  acc[7]);
                acc[8]  = fma2(xt1, wa.x,  acc[8]);
                acc[9]  = fma2(xt1, wa.y,  acc[9]);
                acc[10] = fma2(xt1, wbb.x, acc[10]);
                acc[11] = fma2(xt1, wbb.y, acc[11]);
                acc[12] = fma2(xt1, wc.x,  acc[12]);
                acc[13] = fma2(xt1, wc.y,  acc[13]);
                acc[14] = fma2(xt1, wd.x,  acc[14]);
                acc[15] = fma2(xt1, wd.y,  acc[15]);
                acc[16] = fma2(xt2, wa.x,  acc[16]);
                acc[17] = fma2(xt2, wa.y,  acc[17]);
                acc[18] = fma2(xt2, wbb.x, acc[18]);
                acc[19] = fma2(xt2, wbb.y, acc[19]);
                acc[20] = fma2(xt2, wc.x,  acc[20]);
                acc[21] = fma2(xt2, wc.y,  acc[21]);
                acc[22] = fma2(xt2, wd.x,  acc[22]);
                acc[23] = fma2(xt2, wd.y,  acc[23]);
            }
        }
    }
    __syncthreads();   // everyone done computing before x_s reuse

    // per-(token, eg) top-2 over 16 experts (ascending, strict >)
    float* xch = x_s;  // reuse: [token][eg][4] = 96*16 floats
#pragma unroll
    for (int t = 0; t < 3; ++t) {
        float m0 = -1e30f, m1 = -1e30f;
        int i0 = 0, i1 = 0;
#pragma unroll
        for (int j = 0; j < 8; ++j) {
            unsigned long long a = acc[t * 8 + j];
            float lo = __uint_as_float((unsigned)(a & 0xffffffffull));
            float hi = __uint_as_float((unsigned)(a >> 32));
            int e0 = eg * 16 + 2 * j, e1 = e0 + 1;
            if (lo > m0) { m1 = m0; i1 = i0; m0 = lo; i0 = e0; }
            else if (lo > m1) { m1 = lo; i1 = e0; }
            if (hi > m0) { m1 = m0; i1 = i0; m0 = hi; i0 = e1; }
            else if (hi > m1) { m1 = hi; i1 = e1; }
        }
        float* p = xch + ((ts + 32 * t) * 16 + eg * 4);
        p[0] = m0; p[1] = m1; p[2] = (float)i0; p[3] = (float)i1;
    }
    if (tid < NE) h[tid] = 0;
    __syncthreads();

    // threads 0..95 finalize one token each: merge 4 groups ascending
    if (tid < TOKB) {
        int tok = blockIdx.x * TOKB + tid;
        const float* p0 = xch + tid * 16;
        float m0 = p0[0], m1 = p0[1];
        int i0 = (int)p0[2], i1 = (int)p0[3];
#pragma unroll
        for (int g = 1; g < 4; ++g) {
            const float* p = xch + tid * 16 + g * 4;
            float b0 = p[0], b1 = p[1];
            int jb0 = (int)p[2], jb1 = (int)p[3];
            if (b0 > m0) {
                if (b1 > m0) { m0 = b0; i0 = jb0; m1 = b1; i1 = jb1; }
                else { m1 = m0; i1 = i0; m0 = b0; i0 = jb0; }
            } else if (b0 > m1) { m1 = b0; i1 = jb0; }
        }
        if (tok < N) {
            float tE = expf(m1 - m0);
            float s0 = 1.0f / (1.0f + tE);
            out_idx[2 * tok]     = (float)i0;
            out_idx[2 * tok + 1] = (float)i1;
            out_w[2 * tok]       = s0;
            out_w[2 * tok + 1]   = tE * s0;
            atomicAdd(&h[i0], 1);
            atomicAdd(&h[i1], 1);
        }
    }
    __syncthreads();
    if (tid < NE) g_hist[blockIdx.x * NE + tid] = h[tid];
}

// ---------------------------------------------------------------------------
// K2: per-expert exclusive scan across gemm blocks (one block per expert).
// ---------------------------------------------------------------------------
__global__ void scan_kernel(float* __restrict__ out_cnt, int capacity, int NB) {
    int e = blockIdx.x;
    int t = threadIdx.x;     // 256
    __shared__ int ssum[256];
    int P = (NB + 255) >> 8;
    int s = t * P, eidx = min(NB, s + P);
    int sum = 0;
    for (int b = s; b < eidx; ++b) sum += g_hist[b * NE + e];
    ssum[t] = sum;
    __syncthreads();
    for (int off = 1; off < 256; off <<= 1) {
        int u = (t >= off) ? ssum[t - off] : 0;
        __syncthreads();
        ssum[t] += u;
        __syncthreads();
    }
    int run = ssum[t] - sum;
    for (int b = s; b < eidx; ++b) {
        g_base[b * NE + e] = run;
        run += g_hist[b * NE + e];
    }
    if (t == 255) {
        int total = ssum[255];
        out_cnt[e] = (float)min(total, capacity);
        g_edrop[e] = max(0, total - capacity);
    }
}

// ---------------------------------------------------------------------------
// K3: ordered capacity mask + final weight normalization.
// One warp per gemm block (192 flat slots). Block 0 reduces dropped count.
// ---------------------------------------------------------------------------
__global__ void mask_kernel(const float* __restrict__ idxf, float* __restrict__ wf,
                            float* __restrict__ maskf, float* __restrict__ dropf,
                            int capacity, int flat) {
    int b = blockIdx.x;
    int lane = threadIdx.x;
    if (b == 0 && lane == 0) {
        int tot = 0;
        for (int i = 0; i < NE; ++i) tot += g_edrop[i];
        dropf[0] = (float)tot;
    }
    __shared__ int sc[NE];
    for (int e = lane; e < NE; e += 32) sc[e] = g_base[b * NE + e];
    __syncwarp();

    int s = b * (TOKB * TOPK);
    int e_ = min(flat, s + TOKB * TOPK);
    for (int i0 = s; i0 < e_; i0 += 32) {
        int i = i0 + lane;
        bool valid = (i < e_);
        unsigned am = __ballot_sync(0xffffffffu, valid);
        float m = 0.f, w = 0.f;
        if (valid) {
            int ex = (int)idxf[i];
            unsigned grp = __match_any_sync(am, ex);
            int leader = __ffs(grp) - 1;
            int prior = __popc(grp & ((1u << lane) - 1u));
            int base = 0;
            if (lane == leader) {
                base = sc[ex];
                sc[ex] = base + __popc(grp);
            }
            base = __shfl_sync(am, base, leader);
            int pos = base + prior;
            m = (pos < capacity) ? 1.f : 0.f;
            w = wf[i];
        }
        float mo = __shfl_xor_sync(0xffffffffu, m, 1);
        if (valid) {
            float msum = m + mo;
            maskf[i] = m;
            wf[i] = w * m / (msum + 1e-10f);
        }
        __syncwarp();
    }
}

// ---------------------------------------------------------------------------
extern "C" void kernel_launch(void* const* d_in, const int* in_sizes, int n_in,
                              void* d_out, int out_size) {
    const float* x = (const float*)d_in[0];
    const float* W = (const float*)d_in[1];
    if (n_in >= 2 && in_sizes[0] < in_sizes[1]) {
        const float* tmp = x; x = W; W = tmp;
    }
    int N = ((in_sizes[0] >= in_sizes[1]) ? in_sizes[0] : in_sizes[1]) / HD;
    int flat = N * TOPK;
    int NB = (N + TOKB - 1) / TOKB;

    float* out    = (float*)d_out;
    float* f_idx  = out;
    float* f_w    = out + flat;
    float* f_mask = out + 2 * flat;
    float* f_cnt  = out + 3 * flat;
    float* f_drop = f_cnt + NE;

    int capacity = (int)(((double)N * (double)TOPK / (double)NE) * 1.25);

    int smem_bytes = (2 * TOKB * XSS + 2 * KC * NE) * 4;   // 23552 B
    cudaFuncSetAttribute(gemm_topk_kernel,
                         cudaFuncAttributeMaxDynamicSharedMemorySize, smem_bytes);

    gemm_topk_kernel<<<NB, TPB, smem_bytes>>>(x, W, f_idx, f_w, N);
    scan_kernel<<<NE, 256>>>(f_cnt, capacity, NB);
    mask_kernel<<<NB, 32>>>(f_idx, f_w, f_mask, f_drop, capacity, flat);
}